// round 10
// baseline (speedup 1.0000x reference)
#include <cuda_runtime.h>
#include <math.h>

#define B_   128
#define S_   512
#define T_   36
#define STARTT 34
#define ENDT   35
#define NTHREADS 128

// dynamic smem layout (floats):
//  [0, 18432)        exp(feats) (S,36)   (reused as finalize scratch)
//  [18432, 19728)    raw transitions (36*36)
//  [19728, 19808)    fwd ping-pong: 2 x 40 (34 used, 16B-aligned stride)
//  [19808, 19888)    bwd ping-pong: 2 x 40
//  [19888, 19928)    AV: alpha at meet (34)
//  [19928, 19968)    BV: beta at meet (34)
//  [19968, 19984)    RD: [0..3] len partials, [6..7] gold, [8] gold total, [9] Ksa, [10] Ksb
#define EF  0
#define TR  18432
#define PF  19728
#define PW  19808
#define AV  19888
#define BV  19928
#define RD  19968
#define SMEM_FLOATS 19984
#define SMEM_BYTES  (SMEM_FLOATS * 4)

typedef unsigned long long ull;

__device__ float g_partial[B_];
__device__ int   g_count = 0;

__device__ __forceinline__ ull ffma2(ull a, ull b, ull c) {
    ull d;
    asm("fma.rn.f32x2 %0, %1, %2, %3;" : "=l"(d) : "l"(a), "l"(b), "l"(c));
    return d;
}
__device__ __forceinline__ ull fadd2(ull a, ull b) {
    ull d;
    asm("add.rn.f32x2 %0, %1, %2;" : "=l"(d) : "l"(a), "l"(b));
    return d;
}
__device__ __forceinline__ ull pack2(float lo, float hi) {
    ull d;
    asm("mov.b64 %0, {%1, %2};" : "=l"(d) : "f"(lo), "f"(hi));
    return d;
}
__device__ __forceinline__ void unpack2(ull v, float& lo, float& hi) {
    asm("mov.b64 {%0, %1}, %2;" : "=f"(lo), "=f"(hi) : "l"(v));
}

// One chain step: gather 34-vector (zero-free layout: 32 via 8xLDS.128 + pair via LDS.64),
// renorm factor from element 0, full 34-dot for this lane's main column (Em[17]),
// and a 9-pack half-dot for the lane-pair's extra column (Ex[9], half sel by lane&1).
__device__ __forceinline__ void chain_step(const float* __restrict__ sbuf,
                                           const ull* __restrict__ Em,
                                           const ull* __restrict__ Ex,
                                           int half8,
                                           float& y, float& ypart,
                                           float& sc, int& Ksum)
{
    const ulonglong2* Vp = (const ulonglong2*)sbuf;
    ulonglong2 W[8];
    #pragma unroll
    for (int q = 0; q < 8; q++) W[q] = Vp[q];
    const ull w4 = *(const ull*)(sbuf + 32);          // pair (v32, v33)

    const unsigned p0 = (unsigned)(W[0].x & 0xFFFFFFFFull);
    int k = (int)((p0 >> 23) & 0xFF) - 127;
    k = max(-120, min(120, k));
    Ksum += k;
    sc = __int_as_float((unsigned)(127 - k) << 23);   // 2^-k

    // main: 17 packs, 4 chains
    ull a0 = 0, a1 = 0, a2 = 0, a3 = 0;
    #pragma unroll
    for (int m = 0; m < 16; m++) {
        const ull pm = (m & 1) ? W[m >> 1].y : W[m >> 1].x;
        switch (m & 3) {
            case 0: a0 = ffma2(pm, Em[m], a0); break;
            case 1: a1 = ffma2(pm, Em[m], a1); break;
            case 2: a2 = ffma2(pm, Em[m], a2); break;
            default: a3 = ffma2(pm, Em[m], a3); break;
        }
    }
    a0 = ffma2(w4, Em[16], a0);
    const ull r = fadd2(fadd2(a0, a1), fadd2(a2, a3));
    float lo, hi;
    unpack2(r, lo, hi);
    y = lo + hi;

    // extra half-dot: packs m = half8 .. half8+8 (Ex[8]=0 for half0 kills overlap)
    ull e0 = 0, e1 = 0;
    #pragma unroll
    for (int mm = 0; mm < 9; mm++) {
        const int m = half8 + mm;
        const ull pm = (m == 16) ? w4 : ((m & 1) ? W[m >> 1].y : W[m >> 1].x);
        if (mm & 1) e1 = ffma2(pm, Ex[mm], e1);
        else        e0 = ffma2(pm, Ex[mm], e0);
    }
    const ull re = fadd2(e0, e1);
    float el, eh;
    unpack2(re, el, eh);
    float part = el + eh;
    part += __shfl_xor_sync(0xFFFFFFFFu, part, 1);    // lane pair -> full extra dot
    ypart = part;
}

__global__ void __launch_bounds__(NTHREADS, 1)
crf_kernel(const float* __restrict__ feats,
           const float* __restrict__ transitions,
           const int*   __restrict__ mask,
           const int*   __restrict__ tags,
           float*       __restrict__ out)
{
    extern __shared__ float sh[];
    const int tid  = threadIdx.x;
    const int lane = tid & 31;
    const int wid  = tid >> 5;
    const int b    = blockIdx.x;

    // ---- stage exp(feats[b]) (72KB, (S,36)) + raw transitions, coalesced ----
    {
        const float4* fsrc = (const float4*)(feats + (size_t)b * (S_ * T_));
        float4* fdst = (float4*)(sh + EF);
        #pragma unroll
        for (int i = 0; i < (S_ * T_ / 4) / NTHREADS; i++) {   // 36 iters
            float4 v = fsrc[tid + i * NTHREADS];
            v.x = __expf(v.x); v.y = __expf(v.y);
            v.z = __expf(v.z); v.w = __expf(v.w);
            fdst[tid + i * NTHREADS] = v;
        }
        const float4* tsrc = (const float4*)transitions;
        float4* tdst = (float4*)(sh + TR);
        for (int i = tid; i < (T_ * T_ / 4); i += NTHREADS)
            tdst[i] = tsrc[i];
    }

    // ---- sequence length (mask is a contiguous prefix) ----
    int lsum = 0;
    {
        const int* mrow = mask + b * S_;
        #pragma unroll
        for (int i = 0; i < 4; i++) lsum += mrow[tid + i * NTHREADS];
    }
    #pragma unroll
    for (int off = 16; off > 0; off >>= 1)
        lsum += __shfl_xor_sync(0xFFFFFFFFu, lsum, off);
    if (lane == 0) ((int*)(sh + RD))[wid] = lsum;
    __syncthreads();
    const int len = ((const int*)(sh + RD))[0] + ((const int*)(sh + RD))[1]
                  + ((const int*)(sh + RD))[2] + ((const int*)(sh + RD))[3];
    const int nf = (len - 1) >> 1;     // meet point t = nf

    const int exCol = 32 + ((lane >> 1) & 1);   // extra col/state for this lane pair
    const int half8 = (lane & 1) * 8;           // which half of the 17 packs

    if (wid == 0) {
        // ===== warp 0: FORWARD alpha chain (34 states), t = 1..nf =====
        // main column pack: Em[m] = (E[2m][lane], E[2m+1][lane])
        ull Em[17], Ex[9];
        #pragma unroll
        for (int m = 0; m < 17; m++)
            Em[m] = pack2(__expf(sh[TR + (2 * m) * T_ + lane]),
                          __expf(sh[TR + (2 * m + 1) * T_ + lane]));
        #pragma unroll
        for (int mm = 0; mm < 9; mm++) {
            const int m = half8 + mm;
            Ex[mm] = (half8 == 0 && mm == 8) ? 0ull
                   : pack2(__expf(sh[TR + (2 * m) * T_ + exCol]),
                           __expf(sh[TR + (2 * m + 1) * T_ + exCol]));
        }

        float p  = sh[EF + lane]  * __expf(sh[TR + STARTT * T_ + lane]);
        float px = sh[EF + exCol] * __expf(sh[TR + STARTT * T_ + exCol]);

        int Ks = 0, buf = 0;
        float* pb = sh + PF;
        for (int t = 1; t <= nf; t++) {
            pb[buf * 40 + lane] = p;
            if ((lane & 1) == 0 && lane < 4) pb[buf * 40 + 32 + (lane >> 1)] = px;
            __syncwarp();
            const float eff  = sh[EF + t * T_ + lane];
            const float effx = sh[EF + t * T_ + exCol];
            float y, yp, sc;
            chain_step(pb + buf * 40, Em, Ex, half8, y, yp, sc, Ks);
            p  = y  * (eff  * sc);
            px = yp * (effx * sc);
            buf ^= 1;
        }
        sh[AV + lane] = p;
        if ((lane & 1) == 0 && lane < 4) sh[AV + 32 + (lane >> 1)] = px;
        if (lane == 0) ((int*)(sh + RD))[9] = Ks;
    } else if (wid == 1) {
        // ===== warp 1: BACKWARD beta chain (34 states), t = len-1 .. nf+1 =====
        // main row pack for state i=lane: Em[m] = (E[lane][2m], E[lane][2m+1])
        ull Em[17], Ex[9];
        #pragma unroll
        for (int m = 0; m < 17; m++)
            Em[m] = pack2(__expf(sh[TR + lane * T_ + (2 * m)]),
                          __expf(sh[TR + lane * T_ + (2 * m + 1)]));
        #pragma unroll
        for (int mm = 0; mm < 9; mm++) {
            const int m = half8 + mm;
            Ex[mm] = (half8 == 0 && mm == 8) ? 0ull
                   : pack2(__expf(sh[TR + exCol * T_ + (2 * m)]),
                           __expf(sh[TR + exCol * T_ + (2 * m + 1)]));
        }

        float bc  = __expf(sh[TR + lane  * T_ + ENDT]);   // beta_{len-1}
        float bcx = __expf(sh[TR + exCol * T_ + ENDT]);

        int Ks = 0, buf = 0;
        float* wb = sh + PW;
        float efc  = sh[EF + (len - 1) * T_ + lane];
        float efxc = sh[EF + (len - 1) * T_ + exCol];
        for (int t = len - 1; t > nf; t--) {
            const float q  = bc  * efc;     // q_i = ef_t[i] * beta_t[i]
            const float qx = bcx * efxc;
            wb[buf * 40 + lane] = q;
            if ((lane & 1) == 0 && lane < 4) wb[buf * 40 + 32 + (lane >> 1)] = qx;
            __syncwarp();
            // prefetch next step's ef (index valid: t-1 >= nf >= 127)
            efc  = sh[EF + (t - 1) * T_ + lane];
            efxc = sh[EF + (t - 1) * T_ + exCol];
            float y, yp, sc;
            chain_step(wb + buf * 40, Em, Ex, half8, y, yp, sc, Ks);
            bc  = y  * sc;
            bcx = yp * sc;
            buf ^= 1;
        }
        sh[BV + lane] = bc;
        if ((lane & 1) == 0 && lane < 4) sh[BV + 32 + (lane >> 1)] = bcx;
        if (lane == 0) ((int*)(sh + RD))[10] = Ks;
    } else {
        // ===== warps 2,3: gold score (concurrent with both chains) =====
        const int*   trow = tags  + b * S_;
        const float* frow = feats + (size_t)b * (S_ * T_);
        float g = 0.0f;
        for (int t = tid - 64; t < len; t += 64) {
            const int tg = trow[t];
            const int pv = (t == 0) ? STARTT : trow[t - 1];
            g += __ldg(frow + t * T_ + tg) + sh[TR + pv * T_ + tg];
        }
        #pragma unroll
        for (int off = 16; off > 0; off >>= 1)
            g += __shfl_xor_sync(0xFFFFFFFFu, g, off);
        if (lane == 0) sh[RD + 6 + (wid - 2)] = g;
        asm volatile("bar.sync 3, 64;" ::: "memory");
        if (tid == 64) {
            const float endE = sh[TR + trow[len - 1] * T_ + ENDT];
            sh[RD + 8] = sh[RD + 6] + sh[RD + 7] + endE;
        }
    }

    __syncthreads();

    // ---- combine: Z = sum_{i=0..33} alpha_nf[i] * beta_nf[i]  (warp 0) ----
    if (wid == 0) {
        float contrib = sh[AV + lane] * sh[BV + lane];
        if (lane < 2) contrib += sh[AV + 32 + lane] * sh[BV + 32 + lane];
        #pragma unroll
        for (int off = 16; off > 0; off >>= 1)
            contrib += __shfl_xor_sync(0xFFFFFFFFu, contrib, off);
        if (lane == 0) {
            const int Ks = ((const int*)(sh + RD))[9] + ((const int*)(sh + RD))[10];
            const float fwd = __logf(contrib) + (float)Ks * 0.6931471805599453f;
            g_partial[b] = fwd - sh[RD + 8];
        }
    }

    // ---- fused finalize: last block reduces all partials (deterministic) ----
    __shared__ int lastflag;
    __threadfence();
    if (tid == 0) lastflag = (atomicAdd(&g_count, 1) == B_ - 1);
    __syncthreads();
    if (lastflag) {
        __threadfence();
        volatile const float* gp = g_partial;
        sh[tid] = gp[tid];                    // reuse EF region as scratch
        __syncthreads();
        #pragma unroll
        for (int off = 64; off > 0; off >>= 1) {
            if (tid < off) sh[tid] += sh[tid + off];
            __syncthreads();
        }
        if (tid == 0) {
            out[0] = sh[0] * (1.0f / (float)B_);
            g_count = 0;   // reset for next graph replay
        }
    }
}

extern "C" void kernel_launch(void* const* d_in, const int* in_sizes, int n_in,
                              void* d_out, int out_size)
{
    const float* feats = (const float*)d_in[0];
    const float* trans = (const float*)d_in[1];
    const int*   mask  = (const int*)d_in[2];
    const int*   tags  = (const int*)d_in[3];

    cudaFuncSetAttribute((const void*)crf_kernel,
                         cudaFuncAttributeMaxDynamicSharedMemorySize, SMEM_BYTES);
    crf_kernel<<<B_, NTHREADS, SMEM_BYTES>>>(feats, trans, mask, tags, (float*)d_out);
}

// round 11
// speedup vs baseline: 2.2700x; 2.2700x over previous
#include <cuda_runtime.h>
#include <math.h>

#define B_   128
#define S_   512
#define T_   36
#define STARTT 34
#define ENDT   35
#define NTHREADS 192

// dynamic smem layout (floats):
//  [0, 18432)        exp(feats) for this batch (S*T)   (reused as finalize scratch)
//  [18432, 19728)    raw transitions (36*36)
//  [19728, 19824)    fwd ping-pong: 2 x 48  (each buffer: half0 @ +0, half1 @ +24)
//  [19824, 19920)    bwd ping-pong: 2 x 48
//  [19920, 19968)    AV: alpha at meet
//  [19968, 20016)    BV: beta at meet
//  [20016, 20048)    RD: [0..5] len partials, [6..7] gold, [8] gold total, [9] Ksa, [10] Ksb
#define EF  0
#define TR  18432
#define PF  19728
#define PW  19824
#define AV  19920
#define BV  19968
#define RD  20016
#define SMEM_FLOATS 20048
#define SMEM_BYTES  (SMEM_FLOATS * 4)

typedef unsigned long long ull;

__device__ float g_partial[B_];
__device__ int   g_count = 0;

__device__ __forceinline__ ull ffma2(ull a, ull b, ull c) {
    ull d;
    asm("fma.rn.f32x2 %0, %1, %2, %3;" : "=l"(d) : "l"(a), "l"(b), "l"(c));
    return d;
}
__device__ __forceinline__ ull fadd2(ull a, ull b) {
    ull d;
    asm("add.rn.f32x2 %0, %1, %2;" : "=l"(d) : "l"(a), "l"(b));
    return d;
}
__device__ __forceinline__ ull pack2(float lo, float hi) {
    ull d;
    asm("mov.b64 %0, {%1, %2};" : "=l"(d) : "f"(lo), "f"(hi));
    return d;
}
__device__ __forceinline__ void unpack2(ull v, float& lo, float& hi) {
    asm("mov.b64 {%0, %1}, %2;" : "=f"(lo), "=f"(hi) : "l"(v));
}
__device__ __forceinline__ void bar_arrive64(int id) {
    asm volatile("bar.arrive %0, 64;" :: "r"(id) : "memory");
}
__device__ __forceinline__ void bar_sync64(int id) {
    asm volatile("bar.sync %0, 64;" :: "r"(id) : "memory");
}

// Partial dot over one 17-value half at hb: 16 values as 8 packed pairs + 1 scalar.
__device__ __forceinline__ void half_fma(const float* __restrict__ hb,
                                         const ull* __restrict__ E8, float eS,
                                         ull& acc0, ull& acc1, float& sS, ull& first)
{
    const ulonglong2* W = (const ulonglong2*)hb;
    const ulonglong2 w0 = W[0], w1 = W[1], w2 = W[2], w3 = W[3];
    acc0 = ffma2(w0.x, E8[0], acc0);  acc1 = ffma2(w0.y, E8[1], acc1);
    acc0 = ffma2(w1.x, E8[2], acc0);  acc1 = ffma2(w1.y, E8[3], acc1);
    acc0 = ffma2(w2.x, E8[4], acc0);  acc1 = ffma2(w2.y, E8[5], acc1);
    acc0 = ffma2(w3.x, E8[6], acc0);  acc1 = ffma2(w3.y, E8[7], acc1);
    sS = fmaf(hb[16], eS, sS);
    first = w0.x;
}

// ---- one fwd step; RENORM selects power-of-two rescale (every 2nd step) ----
#define FWD_STEP(BUF, RENORM, TT) do {                                        \
    if (lane < 17) pb[(BUF) * 48 + ownOff + lane] = p;                        \
    bar_arrive64(myArr);                                                      \
    __syncwarp();                                                             \
    const float eff = sh[EF + (TT) * T_ + j];                                 \
    ull a0 = 0, a1 = 0; float sOwn = 0.0f; ull f0own;                         \
    half_fma(pb + (BUF) * 48 + ownOff, Eown, eOwn, a0, a1, sOwn, f0own);      \
    bar_sync64(mySyn);                                                        \
    ull b0 = 0, b1 = 0; float sOth = 0.0f; ull f0oth;                         \
    half_fma(pb + (BUF) * 48 + othOff, Eoth, eOth, b0, b1, sOth, f0oth);      \
    float tail = eff;                                                         \
    if (RENORM) {                                                             \
        const ull h0 = half ? f0oth : f0own;                                  \
        const unsigned p0b = (unsigned)(h0 & 0xFFFFFFFFull);                  \
        int k = (int)((p0b >> 23) & 0xFF) - 127;                              \
        k = max(-120, min(120, k));                                           \
        Ks += k;                                                              \
        tail = eff * __int_as_float((unsigned)(127 - k) << 23);               \
    }                                                                         \
    const ull r = fadd2(fadd2(a0, b0), fadd2(a1, b1));                        \
    float lo, hi; unpack2(r, lo, hi);                                         \
    p = ((lo + hi) + (sOwn + sOth)) * tail;                                   \
} while (0)

// ---- one bwd step; efc holds ef_t (prefetched), reloads for t-1 ----
#define BWD_STEP(BUF, RENORM, TT) do {                                        \
    const float q = bc * efc;                                                 \
    if (lane < 17) wb[(BUF) * 48 + ownOff + lane] = q;                        \
    bar_arrive64(myArr);                                                      \
    __syncwarp();                                                             \
    efc = sh[EF + ((TT) - 1) * T_ + j];   /* prefetch (row >= nf, valid) */   \
    ull a0 = 0, a1 = 0; float sOwn = 0.0f; ull f0own;                         \
    half_fma(wb + (BUF) * 48 + ownOff, Rown, rOwn, a0, a1, sOwn, f0own);      \
    bar_sync64(mySyn);                                                        \
    ull b0 = 0, b1 = 0; float sOth = 0.0f; ull f0oth;                         \
    half_fma(wb + (BUF) * 48 + othOff, Roth, rOth, b0, b1, sOth, f0oth);      \
    const ull r = fadd2(fadd2(a0, b0), fadd2(a1, b1));                        \
    float lo, hi; unpack2(r, lo, hi);                                         \
    const float y = (lo + hi) + (sOwn + sOth);                                \
    if (RENORM) {                                                             \
        const ull h0 = half ? f0oth : f0own;                                  \
        const unsigned p0b = (unsigned)(h0 & 0xFFFFFFFFull);                  \
        int k = (int)((p0b >> 23) & 0xFF) - 127;                              \
        k = max(-120, min(120, k));                                           \
        Ks += k;                                                              \
        bc = y * __int_as_float((unsigned)(127 - k) << 23);                   \
    } else {                                                                  \
        bc = y;                                                               \
    }                                                                         \
} while (0)

__global__ void __launch_bounds__(NTHREADS, 1)
crf_kernel(const float* __restrict__ feats,
           const float* __restrict__ transitions,
           const int*   __restrict__ mask,
           const int*   __restrict__ tags,
           float*       __restrict__ out)
{
    extern __shared__ float sh[];
    const int tid  = threadIdx.x;
    const int lane = tid & 31;
    const int wid  = tid >> 5;
    const int b    = blockIdx.x;

    // ---- stage exp(feats[b]) (72KB) + raw transitions into smem, coalesced ----
    {
        const float4* fsrc = (const float4*)(feats + (size_t)b * (S_ * T_));
        float4* fdst = (float4*)(sh + EF);
        #pragma unroll
        for (int i = 0; i < (S_ * T_ / 4) / NTHREADS; i++) {   // 24 iters
            float4 v = fsrc[tid + i * NTHREADS];
            v.x = __expf(v.x); v.y = __expf(v.y);
            v.z = __expf(v.z); v.w = __expf(v.w);
            fdst[tid + i * NTHREADS] = v;
        }
        const float4* tsrc = (const float4*)transitions;
        float4* tdst = (float4*)(sh + TR);
        for (int i = tid; i < (T_ * T_ / 4); i += NTHREADS)
            tdst[i] = tsrc[i];
    }

    // ---- sequence length (mask is a contiguous prefix) ----
    int lsum = 0;
    {
        const int* mrow = mask + b * S_;
        for (int i = tid; i < S_; i += NTHREADS) lsum += mrow[i];
    }
    #pragma unroll
    for (int off = 16; off > 0; off >>= 1)
        lsum += __shfl_xor_sync(0xFFFFFFFFu, lsum, off);
    if (lane == 0) ((int*)(sh + RD))[wid] = lsum;
    __syncthreads();
    int len = 0;
    #pragma unroll
    for (int i = 0; i < 6; i++) len += ((const int*)(sh + RD))[i];
    const int nf = (len - 1) >> 1;     // meet point t = nf

    const int half = wid & 1;                      // warp's half within its chain
    const int l    = (lane < 17) ? lane : 16;      // pad lanes duplicate col 16
    const int j    = half * 17 + l;                // this lane's column/state, 0..33

    if (wid < 2) {
        // ===== FWD chain (warps 0,1): alpha, t = 1..nf =====
        ull E0[8], E1[8];
        #pragma unroll
        for (int m = 0; m < 8; m++) {
            E0[m] = pack2(__expf(sh[TR + (2 * m) * T_ + j]),
                          __expf(sh[TR + (2 * m + 1) * T_ + j]));
            E1[m] = pack2(__expf(sh[TR + (17 + 2 * m) * T_ + j]),
                          __expf(sh[TR + (18 + 2 * m) * T_ + j]));
        }
        const float e16 = __expf(sh[TR + 16 * T_ + j]);
        const float e33 = __expf(sh[TR + 33 * T_ + j]);
        const ull*  Eown = half ? E1 : E0;
        const ull*  Eoth = half ? E0 : E1;
        const float eOwn = half ? e33 : e16;
        const float eOth = half ? e16 : e33;
        const int   ownOff = half * 24, othOff = 24 - half * 24;
        const int   myArr = 1 + half, mySyn = 2 - half;   // bars 1,2

        float p = sh[EF + j] * __expf(sh[TR + STARTT * T_ + j]);
        int Ks = 0;
        float* pb = sh + PF;
        int t = 1;
        while (t + 1 <= nf) {
            FWD_STEP(0, true,  t);
            FWD_STEP(1, false, t + 1);
            t += 2;
        }
        if (t <= nf) { FWD_STEP(0, true, t); }
        if (lane < 17) sh[AV + j] = p;                    // alpha_nf
        if (half == 0 && lane == 0) ((int*)(sh + RD))[9] = Ks;
    } else if (wid < 4) {
        // ===== BWD chain (warps 2,3): beta, t = len-1 .. nf+1 =====
        ull R0[8], R1[8];
        #pragma unroll
        for (int m = 0; m < 8; m++) {
            R0[m] = pack2(__expf(sh[TR + j * T_ + (2 * m)]),
                          __expf(sh[TR + j * T_ + (2 * m + 1)]));
            R1[m] = pack2(__expf(sh[TR + j * T_ + (17 + 2 * m)]),
                          __expf(sh[TR + j * T_ + (18 + 2 * m)]));
        }
        const float r16 = __expf(sh[TR + j * T_ + 16]);
        const float r33 = __expf(sh[TR + j * T_ + 33]);
        const ull*  Rown = half ? R1 : R0;
        const ull*  Roth = half ? R0 : R1;
        const float rOwn = half ? r33 : r16;
        const float rOth = half ? r16 : r33;
        const int   ownOff = half * 24, othOff = 24 - half * 24;
        const int   myArr = 3 + half, mySyn = 4 - half;   // bars 3,4

        float bc  = __expf(sh[TR + j * T_ + ENDT]);       // beta_{len-1}
        float efc = sh[EF + (len - 1) * T_ + j];          // ef at current t
        int Ks = 0;
        float* wb = sh + PW;
        int t = len - 1;
        while (t - 1 > nf) {
            BWD_STEP(0, true,  t);
            BWD_STEP(1, false, t - 1);
            t -= 2;
        }
        if (t > nf) { BWD_STEP(0, true, t); }
        if (lane < 17) sh[BV + j] = bc;                   // beta_nf
        if (half == 0 && lane == 0) ((int*)(sh + RD))[10] = Ks;
    } else {
        // ===== warps 4,5: gold score (concurrent with both chains) =====
        const int*   trow = tags  + b * S_;
        const float* frow = feats + (size_t)b * (S_ * T_);
        float g = 0.0f;
        for (int t = tid - 128; t < len; t += 64) {
            const int tg = trow[t];
            const int pv = (t == 0) ? STARTT : trow[t - 1];
            g += __ldg(frow + t * T_ + tg) + sh[TR + pv * T_ + tg];
        }
        #pragma unroll
        for (int off = 16; off > 0; off >>= 1)
            g += __shfl_xor_sync(0xFFFFFFFFu, g, off);
        if (lane == 0) sh[RD + 6 + (wid - 4)] = g;
        asm volatile("bar.sync 5, 64;" ::: "memory");
        if (tid == 128) {
            const float endE = sh[TR + trow[len - 1] * T_ + ENDT];
            sh[RD + 8] = sh[RD + 6] + sh[RD + 7] + endE;
        }
    }

    __syncthreads();

    // ---- combine: Z = sum_i alpha_nf[i] * beta_nf[i]  (warp 0) ----
    if (wid == 0) {
        const int j0 = 2 * l;
        const float2 av = *(const float2*)(sh + AV + j0);
        const float2 bv = *(const float2*)(sh + BV + j0);
        float contrib = (lane < 17) ? (av.x * bv.x + av.y * bv.y) : 0.0f;
        #pragma unroll
        for (int off = 16; off > 0; off >>= 1)
            contrib += __shfl_xor_sync(0xFFFFFFFFu, contrib, off);
        if (lane == 0) {
            const int Ks = ((const int*)(sh + RD))[9] + ((const int*)(sh + RD))[10];
            const float fwd = __logf(contrib) + (float)Ks * 0.6931471805599453f;
            g_partial[b] = fwd - sh[RD + 8];
        }
    }

    // ---- fused finalize: last block reduces all partials (deterministic) ----
    __shared__ int lastflag;
    __threadfence();
    if (tid == 0) lastflag = (atomicAdd(&g_count, 1) == B_ - 1);
    __syncthreads();
    if (lastflag) {
        __threadfence();
        volatile const float* gp = g_partial;
        if (tid < B_) sh[tid] = gp[tid];      // reuse EF region as scratch
        __syncthreads();
        #pragma unroll
        for (int off = 64; off > 0; off >>= 1) {
            if (tid < off) sh[tid] += sh[tid + off];
            __syncthreads();
        }
        if (tid == 0) {
            out[0] = sh[0] * (1.0f / (float)B_);
            g_count = 0;   // reset for next graph replay
        }
    }
}

extern "C" void kernel_launch(void* const* d_in, const int* in_sizes, int n_in,
                              void* d_out, int out_size)
{
    const float* feats = (const float*)d_in[0];
    const float* trans = (const float*)d_in[1];
    const int*   mask  = (const int*)d_in[2];
    const int*   tags  = (const int*)d_in[3];

    cudaFuncSetAttribute((const void*)crf_kernel,
                         cudaFuncAttributeMaxDynamicSharedMemorySize, SMEM_BYTES);
    crf_kernel<<<B_, NTHREADS, SMEM_BYTES>>>(feats, trans, mask, tags, (float*)d_out);
}